// round 1
// baseline (speedup 1.0000x reference)
#include <cuda_runtime.h>
#include <cstdint>
#include <math_constants.h>

#define NB      4
#define NQ      8192
#define NA      6890
#define ACHUNKS 4
#define CHUNK   1723            // ceil(6890/4)
#define THREADS1 64
#define QPT      4              // queries per thread
#define QBLK    (THREADS1*QPT)  // 256 queries per stage-1 block
#define QTILES  (NQ/QBLK)       // 32

// scratch: packed (d2_bits << 32) | anchor_idx per (query, chunk)
__device__ unsigned long long g_partial[NB * NQ * ACHUNKS];

__global__ void zero_out_kernel(float* out) {
    if (threadIdx.x < NB) out[threadIdx.x] = 0.0f;
}

__global__ void __launch_bounds__(THREADS1)
stage1_kernel(const float* __restrict__ query, const float* __restrict__ anchor)
{
    __shared__ float4 sA[CHUNK];

    const int bid   = blockIdx.x;
    const int chunk = bid % ACHUNKS;
    const int tile  = (bid / ACHUNKS) % QTILES;
    const int b     = bid / (ACHUNKS * QTILES);

    const int a0     = chunk * CHUNK;
    const int acount = min(CHUNK, NA - a0);

    // stage anchors (x, y, z, 0.5*||a||^2) into smem
    const float* abase = anchor + ((long)b * NA + a0) * 3;
    for (int j = threadIdx.x; j < acount; j += THREADS1) {
        float ax = abase[j * 3 + 0];
        float ay = abase[j * 3 + 1];
        float az = abase[j * 3 + 2];
        sA[j] = make_float4(ax, ay, az, 0.5f * (ax * ax + ay * ay + az * az));
    }
    __syncthreads();

    // per-thread queries (negated coords so metric = fma chain seeded by halfa2)
    float nqx[QPT], nqy[QPT], nqz[QPT], hq2[QPT], best[QPT];
    int   bidx[QPT];
    const int qbase = b * NQ + tile * QBLK;
    #pragma unroll
    for (int q = 0; q < QPT; q++) {
        const int qi = qbase + threadIdx.x + q * THREADS1;
        float qx = query[qi * 3 + 0];
        float qy = query[qi * 3 + 1];
        float qz = query[qi * 3 + 2];
        nqx[q] = -qx; nqy[q] = -qy; nqz[q] = -qz;
        hq2[q] = 0.5f * (qx * qx + qy * qy + qz * qz);
        best[q] = CUDART_INF_F;
        bidx[q] = 0;
    }

    // main scan: metric = halfa2 - q.a  (= (d2 - q2)/2, order-preserving per query)
    #pragma unroll 4
    for (int j = 0; j < acount; j++) {
        const float4 a = sA[j];
        #pragma unroll
        for (int q = 0; q < QPT; q++) {
            float m = fmaf(a.x, nqx[q], fmaf(a.y, nqy[q], fmaf(a.z, nqz[q], a.w)));
            if (m < best[q]) { best[q] = m; bidx[q] = j; }
        }
    }

    // emit packed keys: high 32 = bits of (d2/2) clamped >= 0, low 32 = global idx
    #pragma unroll
    for (int q = 0; q < QPT; q++) {
        const int qi = qbase + threadIdx.x + q * THREADS1;
        float d2h = fmaxf(best[q] + hq2[q], 0.0f);   // nonneg -> float bits order as int
        unsigned long long key =
            ((unsigned long long)__float_as_uint(d2h) << 32) |
            (unsigned int)(a0 + bidx[q]);
        g_partial[(long)qi * ACHUNKS + chunk] = key;
    }
}

__global__ void __launch_bounds__(256)
stage2_kernel(const float* __restrict__ query,
              const float* __restrict__ anchor,
              const float* __restrict__ normals,
              float* __restrict__ out)
{
    const int qi = blockIdx.x * 256 + threadIdx.x;   // 0 .. NB*NQ-1
    const int b  = qi / NQ;

    unsigned long long k = g_partial[(long)qi * ACHUNKS + 0];
    #pragma unroll
    for (int c = 1; c < ACHUNKS; c++)
        k = min(k, g_partial[(long)qi * ACHUNKS + c]);
    const int idx = (int)(k & 0xFFFFFFFFu);

    const float qx = query[qi * 3 + 0];
    const float qy = query[qi * 3 + 1];
    const float qz = query[qi * 3 + 2];

    const long abase = ((long)b * NA + idx) * 3;
    const float dx = qx - anchor[abase + 0];
    const float dy = qy - anchor[abase + 1];
    const float dz = qz - anchor[abase + 2];

    const float l2  = sqrtf(dx * dx + dy * dy + dz * dz);
    float dot = dx * normals[abase + 0] + dy * normals[abase + 1] + dz * normals[abase + 2];
    dot = (l2 <= 0.5f) ? dot : 0.0f;           // mask, exactly like reference
    float coll = (dot < 0.0f) ? 1.0f : 0.0f;

    // warp reduce (each warp is fully inside one batch: NQ % 32 == 0)
    #pragma unroll
    for (int off = 16; off > 0; off >>= 1)
        coll += __shfl_down_sync(0xFFFFFFFFu, coll, off);
    if ((threadIdx.x & 31) == 0)
        atomicAdd(&out[b], coll);
}

extern "C" void kernel_launch(void* const* d_in, const int* in_sizes, int n_in,
                              void* d_out, int out_size)
{
    const float* query   = (const float*)d_in[0];   // [4, 8192, 3]
    const float* anchor  = (const float*)d_in[1];   // [4, 6890, 3]
    const float* normals = (const float*)d_in[2];   // [4, 6890, 3]
    float* out = (float*)d_out;                     // [4, 1]

    zero_out_kernel<<<1, 32>>>(out);
    stage1_kernel<<<NB * QTILES * ACHUNKS, THREADS1>>>(query, anchor);
    stage2_kernel<<<(NB * NQ) / 256, 256>>>(query, anchor, normals, out);
}